// round 1
// baseline (speedup 1.0000x reference)
#include <cuda_runtime.h>
#include <cstdint>

// Problem constants
#define NQ   4096   // queries
#define NR   4096   // table rows
#define NV   128    // vectors per row
#define ND   128    // vector dim
#define KTOP 16

// Scratch: per-(query,row) max score and argmax vector index.
__device__ float         g_rowmax[(size_t)NQ * NR];   // 64 MB
__device__ unsigned char g_rowarg[(size_t)NQ * NR];   // 16 MB

typedef unsigned long long u64;

__device__ __forceinline__ u64 pack2(float x, float y) {
    u64 r; asm("mov.b64 %0, {%1, %2};" : "=l"(r) : "f"(x), "f"(y)); return r;
}
__device__ __forceinline__ void fma2(u64& d, u64 a, u64 b) {
    asm("fma.rn.f32x2 %0, %1, %2, %0;" : "+l"(d) : "l"(a), "l"(b));
}
__device__ __forceinline__ float2 unpack2(u64 a) {
    float lo, hi; asm("mov.b64 {%0, %1}, %2;" : "=f"(lo), "=f"(hi) : "l"(a));
    return make_float2(lo, hi);
}

// ---------------------------------------------------------------------------
// Kernel 1: for CTA (qt, r): scores[128q x 128v] = Qtile @ Trow^T, fused
// max+argmax over v. 256 threads as 16(tx: v-groups) x 16(ty: q-groups),
// each thread an 8q x 8v register tile (as 4 q-pairs x 8 v of f32x2).
// K=128 processed in two halves of 64 so static smem stays < 48 KB.
// Grid: x = qt (fast, 32) so concurrent CTAs share the table row via L2.
// ---------------------------------------------------------------------------
__global__ void __launch_bounds__(256, 2)
score_kernel(const float* __restrict__ Q, const float* __restrict__ T) {
    __shared__ __align__(16) float Qs[64 * 132];  // Qs[k][q], padded stride 132
    __shared__ __align__(16) float Ts[8 * 132];   // Ts[kk][v]

    const int qt  = blockIdx.x;   // 0..31  (fast dim -> table L2 reuse)
    const int r   = blockIdx.y;   // 0..4095
    const int tid = threadIdx.x;
    const int tx  = tid & 15;     // v group: v = tx*8 + j
    const int ty  = tid >> 4;     // q group: q = ty*8 + ...

    const float* Qg = Q + (size_t)qt * 128 * 128;
    const float* Tg = T + (size_t)r * NV * ND;

    u64 acc[4][8];
    #pragma unroll
    for (int i = 0; i < 4; i++)
        #pragma unroll
        for (int j = 0; j < 8; j++) acc[i][j] = 0ull;

    #pragma unroll 1
    for (int kh = 0; kh < 2; kh++) {
        __syncthreads();  // previous phase compute done before Qs overwrite
        // Load Q half-tile transposed: Qs[k][q] = Qg[q*128 + kh*64 + k]
        #pragma unroll
        for (int it = 0; it < 32; it++) {
            int idx = it * 256 + tid;
            int k = idx & 63, q = idx >> 6;
            Qs[k * 132 + q] = Qg[q * 128 + kh * 64 + k];
        }
        // Prefetch table chunk 0 of this half into registers
        float pre[4];
        #pragma unroll
        for (int j = 0; j < 4; j++) {
            int e = tid + 256 * j; int v = e >> 3, kk = e & 7;
            pre[j] = Tg[v * 128 + kh * 64 + kk];
        }
        #pragma unroll 1
        for (int kc = 0; kc < 8; kc++) {
            __syncthreads();  // compute on Ts from prev chunk finished
            #pragma unroll
            for (int j = 0; j < 4; j++) {
                int e = tid + 256 * j; int v = e >> 3, kk = e & 7;
                Ts[kk * 132 + v] = pre[j];
            }
            __syncthreads();  // Ts (and on kc==0, Qs) visible
            if (kc < 7) {
                #pragma unroll
                for (int j = 0; j < 4; j++) {
                    int e = tid + 256 * j; int v = e >> 3, kk = e & 7;
                    pre[j] = Tg[v * 128 + kh * 64 + (kc + 1) * 8 + kk];
                }
            }
            #pragma unroll
            for (int kk = 0; kk < 8; kk++) {
                int lk = kc * 8 + kk;
                const float4* qp = (const float4*)(Qs + lk * 132 + ty * 8);
                float4 qa = qp[0], qb = qp[1];
                const float4* tp = (const float4*)(Ts + kk * 132 + tx * 8);
                float4 ba = tp[0], bb = tp[1];
                u64 a0 = pack2(qa.x, qa.y), a1 = pack2(qa.z, qa.w);
                u64 a2 = pack2(qb.x, qb.y), a3 = pack2(qb.z, qb.w);
                float bv[8] = {ba.x, ba.y, ba.z, ba.w, bb.x, bb.y, bb.z, bb.w};
                #pragma unroll
                for (int j = 0; j < 8; j++) {
                    u64 b2 = pack2(bv[j], bv[j]);
                    fma2(acc[0][j], a0, b2);
                    fma2(acc[1][j], a1, b2);
                    fma2(acc[2][j], a2, b2);
                    fma2(acc[3][j], a3, b2);
                }
            }
        }
    }

    // Epilogue: per q, max+argmax over this thread's 8 v, then butterfly
    // across the 16 tx lanes. Tie-break: LOWEST v index (matches jnp.argmax).
    const float NEG = __int_as_float(0xff800000);
    #pragma unroll
    for (int i = 0; i < 4; i++) {
        float bx = NEG, by = NEG; int jx = 0, jy = 0;
        #pragma unroll
        for (int j = 0; j < 8; j++) {
            float2 f = unpack2(acc[i][j]);
            if (f.x > bx) { bx = f.x; jx = j; }   // strict > keeps lowest j
            if (f.y > by) { by = f.y; jy = j; }
        }
        int vx = tx * 8 + jx, vy = tx * 8 + jy;
        #pragma unroll
        for (int off = 8; off; off >>= 1) {
            float ox = __shfl_xor_sync(0xffffffffu, bx, off);
            int   oi = __shfl_xor_sync(0xffffffffu, vx, off);
            if (ox > bx || (ox == bx && oi < vx)) { bx = ox; vx = oi; }
            float oy = __shfl_xor_sync(0xffffffffu, by, off);
            int   oj = __shfl_xor_sync(0xffffffffu, vy, off);
            if (oy > by || (oy == by && oj < vy)) { by = oy; vy = oj; }
        }
        if (tx == 0) {
            int q0 = qt * 128 + ty * 8 + 2 * i;
            size_t o0 = (size_t)q0 * NR + r;
            g_rowmax[o0]      = bx; g_rowarg[o0]      = (unsigned char)vx;
            g_rowmax[o0 + NR] = by; g_rowarg[o0 + NR] = (unsigned char)vy;
        }
    }
}

// ---------------------------------------------------------------------------
// Kernel 2: one warp per query. 16 rounds of warp-argmax over 4096 row-max
// scores. Exclusion is stateless: round i takes the max among entries
// strictly below the previous pick in (score desc, row-index desc) order —
// exactly jnp.argsort(stable asc) reversed. Then gather values/scores/ids.
// Output layout (f32): [values 4096*16*128 | scores 4096*16 | ids 4096*16].
// ---------------------------------------------------------------------------
__global__ void topk_kernel(const float* __restrict__ T, float* __restrict__ out) {
    int gw   = (blockIdx.x * blockDim.x + threadIdx.x) >> 5;
    int lane = threadIdx.x & 31;
    if (gw >= NQ) return;
    const int q = gw;
    const float* sc = g_rowmax + (size_t)q * NR;

    float pv = __int_as_float(0x7f800000);  // +inf: everything is "below" it
    int   pr = NR;

    for (int i = 0; i < KTOP; i++) {
        float bv = __int_as_float(0xff800000); int br = -1;
        for (int j = lane; j < NR; j += 32) {
            float v = sc[j];
            bool below = (v < pv) || (v == pv && j < pr);
            if (below && (v > bv || (v == bv && j > br))) { bv = v; br = j; }
        }
        #pragma unroll
        for (int off = 16; off; off >>= 1) {
            float ov = __shfl_xor_sync(0xffffffffu, bv, off);
            int   orr = __shfl_xor_sync(0xffffffffu, br, off);
            if (ov > bv || (ov == bv && orr > br)) { bv = ov; br = orr; }
        }
        pv = bv; pr = br;  // converged on all lanes

        int vidx = g_rowarg[(size_t)q * NR + br];
        const float* src = T + ((size_t)br * NV + vidx) * ND;
        float* dst = out + ((size_t)q * KTOP + i) * ND;
        for (int d = lane; d < ND; d += 32) dst[d] = src[d];
        if (lane == 0) {
            out[(size_t)NQ * KTOP * ND + (size_t)q * KTOP + i] = bv;
            out[(size_t)NQ * KTOP * ND + (size_t)NQ * KTOP + (size_t)q * KTOP + i] =
                (float)(br * NV + vidx);
        }
    }
}

extern "C" void kernel_launch(void* const* d_in, const int* in_sizes, int n_in,
                              void* d_out, int out_size) {
    const float* Q = (const float*)d_in[0];
    const float* T = (const float*)d_in[1];
    // Defensive: queries (524288 elems) vs table (67108864 elems)
    if (n_in >= 2 && in_sizes[0] > in_sizes[1]) { const float* t = Q; Q = T; T = t; }

    dim3 g1(32, 4096);          // qt fast-varying -> table row shared via L2
    score_kernel<<<g1, 256>>>(Q, T);

    int warps = NQ;             // one warp per query
    topk_kernel<<<(warps * 32 + 255) / 256, 256>>>(T, (float*)d_out);
}

// round 5
// speedup vs baseline: 4.9910x; 4.9910x over previous
#include <cuda_runtime.h>
#include <cstdint>

typedef unsigned int u32;
typedef unsigned long long u64;

#define NQ   4096
#define NR   4096
#define NV   128
#define ND   128
#define KTOP 16
#define CAND 96     // candidate rows per query (cap)
#define RCAP 768    // per-row query-list capacity
#define CQ   16     // queries per sweep in exact kernel

// ---------------- device globals ----------------
__device__ u32   g_Tbf16[(size_t)NR * NV * ND / 2];   // 128 MB bf16x2
__device__ u32   g_Qbf16[(size_t)NQ * ND / 2];        // 1 MB
__device__ float g_rowmax[(size_t)NQ * NR];           // 64 MB approx scores
__device__ int   g_rowcnt[NR];
__device__ u32   g_rowlist[(size_t)NR * RCAP];        // (q<<7)|slot
__device__ int   g_cand_row[(size_t)NQ * CAND];
__device__ u64   g_cand_key[(size_t)NQ * CAND];       // (okey(score)<<32)|(127-v)
__device__ int   g_cand_cnt[NQ];

// ---------------- helpers ----------------
__device__ __forceinline__ u32 okey(float f) {
    u32 b = __float_as_uint(f);
    return (b & 0x80000000u) ? ~b : (b | 0x80000000u);
}
__device__ __forceinline__ float unokey(u32 u) {
    u32 b = (u & 0x80000000u) ? (u & 0x7fffffffu) : ~u;
    return __uint_as_float(b);
}
__device__ __forceinline__ u32 pack_bf16x2(float lo, float hi) {
    u32 p; asm("cvt.rn.bf16x2.f32 %0, %1, %2;" : "=r"(p) : "f"(hi), "f"(lo));
    return p;
}
__device__ __forceinline__ float fmas(float a, float b, float c) {
    float d; asm("fma.rn.f32 %0, %1, %2, %3;" : "=f"(d) : "f"(a), "f"(b), "f"(c));
    return d;
}

#define MMA16816(c, A0, A1, A2, A3, B0, B1) \
    asm volatile("mma.sync.aligned.m16n8k16.row.col.f32.bf16.bf16.f32 " \
        "{%0,%1,%2,%3}, {%4,%5,%6,%7}, {%8,%9}, {%0,%1,%2,%3};" \
        : "+f"((c)[0]), "+f"((c)[1]), "+f"((c)[2]), "+f"((c)[3]) \
        : "r"(A0), "r"(A1), "r"(A2), "r"(A3), "r"(B0), "r"(B1))

// ---------------- conversion / init ----------------
__global__ void conv_T_kernel(const float* __restrict__ T) {
    size_t i = ((size_t)blockIdx.x * 256 + threadIdx.x) * 4;
    const float4* s = (const float4*)(T + i * 2);
    float4 a = s[0], b = s[1];
    uint4 o;
    o.x = pack_bf16x2(a.x, a.y); o.y = pack_bf16x2(a.z, a.w);
    o.z = pack_bf16x2(b.x, b.y); o.w = pack_bf16x2(b.z, b.w);
    *(uint4*)(g_Tbf16 + i) = o;
}
__global__ void conv_Q_kernel(const float* __restrict__ Q) {
    size_t i = (size_t)blockIdx.x * 256 + threadIdx.x;
    float2 a = ((const float2*)Q)[i];
    g_Qbf16[i] = pack_bf16x2(a.x, a.y);
}
__global__ void init_kernel() {
    int i = blockIdx.x * 256 + threadIdx.x;
    if (i < NR) g_rowcnt[i] = 0;
    if (i < NQ * CAND) g_cand_key[i] = 0ull;
}

// ============================================================================
// Phase A: approx scoring with mma.sync bf16 (audited; selection-only role).
// ============================================================================
__global__ void __launch_bounds__(256, 2)
score_mma_kernel() {
    __shared__ uint4 Qs4[128 * 16];   // rotated: grp' = (grp + q%8)%16
    __shared__ uint4 Ts4[128 * 5];    // stride 40 bf16 per v
    __shared__ u32   red[128];

    const u32* Qs = (const u32*)Qs4;
    const u32* Ts = (const u32*)Ts4;

    const int tid  = threadIdx.x;
    const int lane = tid & 31;
    const int wid  = tid >> 5;
    const int wm   = wid >> 2;
    const int wn   = wid & 3;
    const int g    = lane >> 2;
    const int tg   = lane & 3;
    const int qt   = blockIdx.x;
    const int rg   = blockIdx.y;

    {
        int q = tid >> 1, khalf = tid & 1;
        const uint4* src = (const uint4*)(g_Qbf16 + ((size_t)(qt * 128 + q)) * 64)
                           + khalf * 8;
        #pragma unroll
        for (int gi = 0; gi < 8; gi++) {
            int sg = khalf * 8 + gi;
            int dg = (sg + (q & 7)) & 15;
            Qs4[q * 16 + dg] = src[gi];
        }
    }
    if (tid < 128) red[tid] = 0;

    uint4 pf0, pf1;
    const int u0 = tid * 2, v0 = u0 >> 2, p0 = u0 & 3;
    const int u1 = u0 + 1, v1 = u1 >> 2, p1 = u1 & 3;
    {
        size_t r = (size_t)rg * 32;
        const uint4* base = (const uint4*)g_Tbf16 + r * 2048;
        pf0 = __ldg(base + v0 * 16 + p0);
        pf1 = __ldg(base + v1 * 16 + p1);
    }

    float rowreg[8];

    #pragma unroll 1
    for (int ri = 0; ri < 32; ri++) {
        float acc[4][4][4];
        #pragma unroll
        for (int mt = 0; mt < 4; mt++)
            #pragma unroll
            for (int nt = 0; nt < 4; nt++)
                #pragma unroll
                for (int c = 0; c < 4; c++) acc[mt][nt][c] = 0.f;

        #pragma unroll 1
        for (int kc = 0; kc < 4; kc++) {
            __syncthreads();
            ((uint4*)Ts)[v0 * 5 + p0] = pf0;
            ((uint4*)Ts)[v1 * 5 + p1] = pf1;
            int cidx = ri * 4 + kc;
            if (cidx + 1 < 128) {
                size_t r = (size_t)rg * 32 + ((cidx + 1) >> 2);
                int kcn = (cidx + 1) & 3;
                const uint4* base = (const uint4*)g_Tbf16 + r * 2048 + kcn * 4;
                pf0 = __ldg(base + v0 * 16 + p0);
                pf1 = __ldg(base + v1 * 16 + p1);
            }
            __syncthreads();

            #pragma unroll
            for (int ks = 0; ks < 2; ks++) {
                const int grpbase = kc * 4 + ks * 2;
                u32 a[4][4];
                #pragma unroll
                for (int mt = 0; mt < 4; mt++) {
                    int qlo = wm * 64 + mt * 16 + g;
                    int rot = qlo & 7;
                    int g0 = (grpbase + rot) & 15;
                    int g1 = (grpbase + 1 + rot) & 15;
                    const u32* r0 = Qs + qlo * 64;
                    const u32* r1 = Qs + (qlo + 8) * 64;
                    a[mt][0] = r0[g0 * 4 + tg];
                    a[mt][1] = r1[g0 * 4 + tg];
                    a[mt][2] = r0[g1 * 4 + tg];
                    a[mt][3] = r1[g1 * 4 + tg];
                }
                u32 b[4][2];
                #pragma unroll
                for (int nt = 0; nt < 4; nt++) {
                    const u32* tr = Ts + (wn * 32 + nt * 8 + g) * 20 + ks * 8;
                    b[nt][0] = tr[tg];
                    b[nt][1] = tr[4 + tg];
                }
                #pragma unroll
                for (int mt = 0; mt < 4; mt++)
                    #pragma unroll
                    for (int nt = 0; nt < 4; nt++)
                        MMA16816(acc[mt][nt], a[mt][0], a[mt][1], a[mt][2], a[mt][3],
                                 b[nt][0], b[nt][1]);
            }
        }

        const float NEG = __int_as_float(0xff800000);
        #pragma unroll
        for (int mt = 0; mt < 4; mt++) {
            float m0 = NEG, m1 = NEG;
            #pragma unroll
            for (int nt = 0; nt < 4; nt++) {
                m0 = fmaxf(m0, fmaxf(acc[mt][nt][0], acc[mt][nt][1]));
                m1 = fmaxf(m1, fmaxf(acc[mt][nt][2], acc[mt][nt][3]));
            }
            m0 = fmaxf(m0, __shfl_xor_sync(0xffffffffu, m0, 1));
            m0 = fmaxf(m0, __shfl_xor_sync(0xffffffffu, m0, 2));
            m1 = fmaxf(m1, __shfl_xor_sync(0xffffffffu, m1, 1));
            m1 = fmaxf(m1, __shfl_xor_sync(0xffffffffu, m1, 2));
            if (tg == 0) {
                int qb = wm * 64 + mt * 16 + g;
                atomicMax(&red[qb], okey(m0));
                atomicMax(&red[qb + 8], okey(m1));
            }
        }
        __syncthreads();
        if (tid < 128) {
            rowreg[ri & 7] = unokey(red[tid]);
            red[tid] = 0;
            if ((ri & 7) == 7) {
                float* dst = g_rowmax + (size_t)(qt * 128 + tid) * NR
                           + rg * 32 + (ri & ~7);
                ((float4*)dst)[0] = make_float4(rowreg[0], rowreg[1], rowreg[2], rowreg[3]);
                ((float4*)dst)[1] = make_float4(rowreg[4], rowreg[5], rowreg[6], rowreg[7]);
            }
        }
    }
}

// ============================================================================
// Phase B: per-query candidate selection (approx rank-40 threshold, cap 96).
// ============================================================================
__global__ void select_kernel() {
    __shared__ u32 hist[256];
    __shared__ u32 s_b1, s_need, s_thr, s_cnt;
    const int tid = threadIdx.x;
    const int q = blockIdx.x;
    const float* sc = g_rowmax + (size_t)q * NR;

    hist[tid] = 0;
    __syncthreads();
    for (int j = tid; j < NR; j += 256) atomicAdd(&hist[okey(sc[j]) >> 24], 1u);
    __syncthreads();
    if (tid == 0) {
        u32 cum = 0;
        for (int b = 255; b >= 0; b--) {
            if (cum + hist[b] >= 40u) { s_b1 = (u32)b; s_need = 40u - cum; break; }
            cum += hist[b];
        }
    }
    __syncthreads();
    u32 b1 = s_b1, need = s_need;
    hist[tid] = 0;
    __syncthreads();
    for (int j = tid; j < NR; j += 256) {
        u32 u = okey(sc[j]);
        if ((u >> 24) == b1) atomicAdd(&hist[(u >> 16) & 255u], 1u);
    }
    __syncthreads();
    if (tid == 0) {
        u32 cum = 0; u32 b2 = 0;
        for (int b = 255; b >= 0; b--) { cum += hist[b]; if (cum >= need) { b2 = (u32)b; break; } }
        s_thr = (b1 << 8) | b2;
        s_cnt = 0;
    }
    __syncthreads();
    u32 thr = s_thr;
    for (int j = tid; j < NR; j += 256) {
        u32 u = okey(sc[j]);
        if ((u >> 16) >= thr) {
            u32 pos = atomicAdd(&s_cnt, 1u);
            if (pos < CAND) {
                g_cand_row[(size_t)q * CAND + pos] = j;
                int p2 = atomicAdd(&g_rowcnt[j], 1);
                if (p2 < RCAP) g_rowlist[(size_t)j * RCAP + p2] = ((u32)q << 7) | pos;
            }
        }
    }
    __syncthreads();
    if (tid == 0) g_cand_cnt[q] = (int)(s_cnt < CAND ? s_cnt : CAND);
}

// ============================================================================
// Phase C: exact recompute, BITWISE-matching reference: each score is an
// in-order fp32 FMA chain over k=0..127 with a single accumulator (this
// exact form matched the reference bitwise in round 1). CTA per row,
// 256 thr = 4 query-slots x 64 vectors; T half-row staged in smem
// (stride 132 -> conflict-free LDS.128); per-query argmax via u64 keys
// (okey(score)<<32 | 127-v): ties -> lowest v, matching jnp.argmax.
// ============================================================================
__global__ void __launch_bounds__(256)
exact_kernel(const float* __restrict__ Q, const float* __restrict__ T) {
    __shared__ __align__(16) float Ts[64 * 132];   // 33792 B
    __shared__ __align__(16) float Qs[CQ * 128];   // 8192 B
    __shared__ u64 sres[CQ];
    __shared__ u32 sent[CQ];

    const int tid = threadIdx.x;
    const int r = blockIdx.x;
    int nq = g_rowcnt[r];
    if (nq > RCAP) nq = RCAP;
    if (nq == 0) return;
    const int g = tid >> 6;      // query slot group 0..3
    const int v = tid & 63;      // vector within half

    #pragma unroll 1
    for (int h = 0; h < 2; h++) {
        __syncthreads();   // previous half's compute done before Ts overwrite
        {
            const float4* src = (const float4*)(T + (size_t)r * NV * ND
                                                + (size_t)h * 64 * ND);
            #pragma unroll
            for (int i = 0; i < 8; i++) {
                int e = i * 256 + tid;          // 0..2047 float4
                int vv = e >> 5, k4 = e & 31;
                *(float4*)(Ts + vv * 132 + k4 * 4) = src[e];
            }
        }
        #pragma unroll 1
        for (int s = 0; s < nq; s += CQ) {
            int cnt = nq - s; if (cnt > CQ) cnt = CQ;
            __syncthreads();   // Ts ready / prev sweep fully done
            if (tid < CQ) {
                sres[tid] = 0ull;
                sent[tid] = (tid < cnt) ? g_rowlist[(size_t)r * RCAP + s + tid] : 0u;
            }
            __syncthreads();
            #pragma unroll
            for (int i = 0; i < 2; i++) {
                int e = i * 256 + tid;          // 0..511 float4
                int qq = e >> 5, k4 = e & 31;
                if (qq < cnt) {
                    int qidx = (int)(sent[qq] >> 7);
                    *(float4*)(Qs + qq * 128 + k4 * 4) =
                        ((const float4*)(Q + (size_t)qidx * ND))[k4];
                }
            }
            __syncthreads();

            float a0 = 0.f, a1 = 0.f, a2 = 0.f, a3 = 0.f;
            const float* tv = Ts + v * 132;
            const float* q0 = Qs + (g * 4 + 0) * 128;
            const float* q1 = Qs + (g * 4 + 1) * 128;
            const float* q2 = Qs + (g * 4 + 2) * 128;
            const float* q3 = Qs + (g * 4 + 3) * 128;
            #pragma unroll 8
            for (int k = 0; k < 128; k += 4) {
                float4 t4 = *(const float4*)(tv + k);
                float4 x0 = *(const float4*)(q0 + k);
                float4 x1 = *(const float4*)(q1 + k);
                float4 x2 = *(const float4*)(q2 + k);
                float4 x3 = *(const float4*)(q3 + k);
                a0 = fmas(x0.x, t4.x, a0); a0 = fmas(x0.y, t4.y, a0);
                a0 = fmas(x0.z, t4.z, a0); a0 = fmas(x0.w, t4.w, a0);
                a1 = fmas(x1.x, t4.x, a1); a1 = fmas(x1.y, t4.y, a1);
                a1 = fmas(x1.z, t4.z, a1); a1 = fmas(x1.w, t4.w, a1);
                a2 = fmas(x2.x, t4.x, a2); a2 = fmas(x2.y, t4.y, a2);
                a2 = fmas(x2.z, t4.z, a2); a2 = fmas(x2.w, t4.w, a2);
                a3 = fmas(x3.x, t4.x, a3); a3 = fmas(x3.y, t4.y, a3);
                a3 = fmas(x3.z, t4.z, a3); a3 = fmas(x3.w, t4.w, a3);
            }
            u64 vb = (u64)(u32)(127 - (h * 64 + v));
            atomicMax(&sres[g * 4 + 0], ((u64)okey(a0) << 32) | vb);
            atomicMax(&sres[g * 4 + 1], ((u64)okey(a1) << 32) | vb);
            atomicMax(&sres[g * 4 + 2], ((u64)okey(a2) << 32) | vb);
            atomicMax(&sres[g * 4 + 3], ((u64)okey(a3) << 32) | vb);
            __syncthreads();
            if (tid < cnt) {
                u32 ent = sent[tid];
                int q = (int)(ent >> 7), slot = (int)(ent & 127u);
                atomicMax(&g_cand_key[(size_t)q * CAND + slot], sres[tid]);
            }
        }
    }
}

// ============================================================================
// Phase D: exact top-16 among <=96 candidates + gather (score desc, row desc).
// Output: [values 4096*16*128 | scores 4096*16 | ids 4096*16] (f32).
// ============================================================================
__global__ void final_kernel(const float* __restrict__ T, float* __restrict__ out) {
    int gw = (blockIdx.x * blockDim.x + threadIdx.x) >> 5;
    int lane = threadIdx.x & 31;
    if (gw >= NQ) return;
    const int q = gw;
    int cnt = g_cand_cnt[q];

    u64 key[3]; int argv[3];
    #pragma unroll
    for (int s = 0; s < 3; s++) {
        int idx = lane + 32 * s;
        key[s] = 0; argv[s] = 0;
        if (idx < cnt) {
            u64 ck = g_cand_key[(size_t)q * CAND + idx];
            int rw = g_cand_row[(size_t)q * CAND + idx];
            argv[s] = 127 - (int)(ck & 127u);
            key[s] = (ck & 0xffffffff00000000ull) | (u32)rw;
        }
    }

    for (int i = 0; i < KTOP; i++) {
        u64 m = 0;
        #pragma unroll
        for (int s = 0; s < 3; s++) m = key[s] > m ? key[s] : m;
        #pragma unroll
        for (int off = 16; off; off >>= 1) {
            u64 o = __shfl_xor_sync(0xffffffffu, m, off);
            if (o > m) m = o;
        }
        int have = 0;
        #pragma unroll
        for (int s = 2; s >= 0; s--) if (m && key[s] == m) have = s + 1;
        int myarg = have ? argv[have - 1] : 0;
        unsigned bal = __ballot_sync(0xffffffffu, have != 0);
        int srcl = __ffs(bal) - 1;
        int av = __shfl_sync(0xffffffffu, myarg, srcl);
        int hs = __shfl_sync(0xffffffffu, have, srcl);
        if (lane == srcl) key[hs - 1] = 0;
        int row = (int)(m & 0xffffffffull);
        float score = unokey((u32)(m >> 32));

        const float4* src = (const float4*)(T + ((size_t)row * NV + av) * ND);
        float4* dst = (float4*)(out + ((size_t)q * KTOP + i) * ND);
        dst[lane] = src[lane];
        if (lane == 0) {
            out[(size_t)NQ * KTOP * ND + (size_t)q * KTOP + i] = score;
            out[(size_t)NQ * KTOP * ND + (size_t)NQ * KTOP + (size_t)q * KTOP + i] =
                (float)(row * NV + av);
        }
    }
}

// ============================================================================
extern "C" void kernel_launch(void* const* d_in, const int* in_sizes, int n_in,
                              void* d_out, int out_size) {
    const float* Q = (const float*)d_in[0];
    const float* T = (const float*)d_in[1];
    if (n_in >= 2 && in_sizes[0] > in_sizes[1]) { const float* t = Q; Q = T; T = t; }

    init_kernel<<<(NQ * CAND + 255) / 256, 256>>>();
    conv_T_kernel<<<32768, 256>>>(T);
    conv_Q_kernel<<<1024, 256>>>(Q);

    score_mma_kernel<<<dim3(32, 128), 256>>>();
    select_kernel<<<NQ, 256>>>();
    exact_kernel<<<NR, 256>>>(Q, T);
    final_kernel<<<(NQ * 32 + 255) / 256, 256>>>(T, (float*)d_out);
}

// round 6
// speedup vs baseline: 5.8340x; 1.1689x over previous
#include <cuda_runtime.h>
#include <cstdint>

typedef unsigned int u32;
typedef unsigned long long u64;

#define NQ   4096
#define NR   4096
#define NV   128
#define ND   128
#define KTOP 16
#define CAND 96     // candidate rows per query (cap)
#define RCAP 768    // per-row query-list capacity
#define CQ   16     // queries per sweep in exact kernel

// ---------------- device globals ----------------
__device__ u32   g_Tfp8[(size_t)NR * NV * ND / 4];    // 64 MB e4m3
__device__ u32   g_Qfp8[(size_t)NQ * ND / 4];         // 512 KB
__device__ float g_rowmax[(size_t)NQ * NR];           // 64 MB approx scores
__device__ int   g_rowcnt[NR];
__device__ u32   g_rowlist[(size_t)NR * RCAP];        // (q<<7)|slot
__device__ int   g_cand_row[(size_t)NQ * CAND];
__device__ u64   g_cand_key[(size_t)NQ * CAND];       // (okey(score)<<32)|(127-v)
__device__ int   g_cand_cnt[NQ];

// ---------------- helpers ----------------
__device__ __forceinline__ u32 okey(float f) {
    u32 b = __float_as_uint(f);
    return (b & 0x80000000u) ? ~b : (b | 0x80000000u);
}
__device__ __forceinline__ float unokey(u32 u) {
    u32 b = (u & 0x80000000u) ? (u & 0x7fffffffu) : ~u;
    return __uint_as_float(b);
}
__device__ __forceinline__ float fmas(float a, float b, float c) {
    float d; asm("fma.rn.f32 %0, %1, %2, %3;" : "=f"(d) : "f"(a), "f"(b), "f"(c));
    return d;
}
// pack 4 consecutive f32 -> 4 e4m3 bytes (little-endian: byte0 = elem0)
__device__ __forceinline__ u32 pack_e4m3x4(float4 a) {
    unsigned short h0, h1; u32 r;
    asm("cvt.rn.satfinite.e4m3x2.f32 %0, %1, %2;" : "=h"(h0) : "f"(a.y), "f"(a.x));
    asm("cvt.rn.satfinite.e4m3x2.f32 %0, %1, %2;" : "=h"(h1) : "f"(a.w), "f"(a.z));
    asm("mov.b32 %0, {%1, %2};" : "=r"(r) : "h"(h0), "h"(h1));
    return r;
}

#define MMAFP8(c, A, B) \
    asm volatile("mma.sync.aligned.m16n8k32.row.col.f32.e4m3.e4m3.f32 " \
        "{%0,%1,%2,%3}, {%4,%5,%6,%7}, {%8,%9}, {%0,%1,%2,%3};" \
        : "+f"((c)[0]), "+f"((c)[1]), "+f"((c)[2]), "+f"((c)[3]) \
        : "r"((A)[0]), "r"((A)[1]), "r"((A)[2]), "r"((A)[3]), \
          "r"((B)[0]), "r"((B)[1]))

// ---------------- conversion / init ----------------
__global__ void conv_T_kernel(const float* __restrict__ T) {
    size_t i = (size_t)blockIdx.x * 256 + threadIdx.x;   // 8 floats -> uint2
    const float4* s = (const float4*)T + i * 2;
    ((uint2*)g_Tfp8)[i] = make_uint2(pack_e4m3x4(s[0]), pack_e4m3x4(s[1]));
}
__global__ void conv_Q_kernel(const float* __restrict__ Q) {
    size_t i = (size_t)blockIdx.x * 256 + threadIdx.x;
    const float4* s = (const float4*)Q + i * 2;
    ((uint2*)g_Qfp8)[i] = make_uint2(pack_e4m3x4(s[0]), pack_e4m3x4(s[1]));
}
__global__ void init_kernel() {
    int i = blockIdx.x * 256 + threadIdx.x;
    if (i < NR) g_rowcnt[i] = 0;
    if (i < NQ * CAND) g_cand_key[i] = 0ull;
}

// ============================================================================
// Phase A: approx scoring, fp8 e4m3 mma.sync.m16n8k32.
// CTA = (qtile 128q, rowgroup 32 rows), 256 thr = 8 warps (2m x 4n),
// warp = 64q x 32v. Q fragments (full K=128) hoisted into 64 registers;
// T row staged per-iteration in stride-36-u32 padded smem (conflict-free).
// Fused epilogue: per-q max over 128 v -> g_rowmax[q][r].
// ============================================================================
__global__ void __launch_bounds__(256, 1)
score_mma_kernel() {
    __shared__ u32 Qs[128 * 36];   // 18 KB (stride 36: banks (4g+tg) distinct)
    __shared__ u32 Ts[128 * 36];   // 18 KB
    __shared__ u32 red[128];

    const int tid  = threadIdx.x;
    const int lane = tid & 31;
    const int wid  = tid >> 5;
    const int wm   = wid >> 2;     // 0..1
    const int wn   = wid & 3;      // 0..3
    const int g    = lane >> 2;    // 0..7
    const int tg   = lane & 3;     // 0..3
    const int qt   = blockIdx.x;   // 0..31 (fast -> L2 row sharing)
    const int rg   = blockIdx.y;   // 0..127

    // stage Q tile (128 x 32 u32) into padded smem
    #pragma unroll
    for (int i = 0; i < 16; i++) {
        int e = i * 256 + tid;
        int q = e >> 5, j = e & 31;
        Qs[q * 36 + j] = g_Qfp8[((size_t)(qt * 128) + q) * 32 + j];
    }
    if (tid < 128) red[tid] = 0;
    __syncthreads();

    // hoist A fragments for full K into registers: A[ks][mt][4]
    u32 A[4][4][4];
    #pragma unroll
    for (int ks = 0; ks < 4; ks++)
        #pragma unroll
        for (int mt = 0; mt < 4; mt++) {
            int qlo = wm * 64 + mt * 16 + g;
            const u32* r0 = Qs + qlo * 36 + ks * 8;
            const u32* r1 = Qs + (qlo + 8) * 36 + ks * 8;
            A[ks][mt][0] = r0[tg];
            A[ks][mt][1] = r1[tg];
            A[ks][mt][2] = r0[4 + tg];
            A[ks][mt][3] = r1[4 + tg];
        }

    // prefetch row 0 (16 KB = 1024 uint4; 4 per thread)
    const uint4* base = (const uint4*)g_Tfp8 + (size_t)(rg * 32) * 1024;
    uint4 pf[4];
    #pragma unroll
    for (int i = 0; i < 4; i++) pf[i] = __ldg(base + i * 256 + tid);

    float rowreg[8];

    #pragma unroll 1
    for (int ri = 0; ri < 32; ri++) {
        __syncthreads();   // previous row's fragments consumed
        #pragma unroll
        for (int i = 0; i < 4; i++) {
            int e = i * 256 + tid;
            int v = e >> 3, p = e & 7;
            *(uint4*)(Ts + v * 36 + p * 4) = pf[i];
        }
        if (ri + 1 < 32) {
            #pragma unroll
            for (int i = 0; i < 4; i++)
                pf[i] = __ldg(base + (size_t)(ri + 1) * 1024 + i * 256 + tid);
        }
        __syncthreads();   // row staged

        float acc[4][4][4];
        #pragma unroll
        for (int mt = 0; mt < 4; mt++)
            #pragma unroll
            for (int nt = 0; nt < 4; nt++)
                #pragma unroll
                for (int c = 0; c < 4; c++) acc[mt][nt][c] = 0.f;

        #pragma unroll
        for (int ks = 0; ks < 4; ks++) {
            u32 b[4][2];
            #pragma unroll
            for (int nt = 0; nt < 4; nt++) {
                const u32* tr = Ts + (wn * 32 + nt * 8 + g) * 36 + ks * 8;
                b[nt][0] = tr[tg];
                b[nt][1] = tr[4 + tg];
            }
            #pragma unroll
            for (int mt = 0; mt < 4; mt++)
                #pragma unroll
                for (int nt = 0; nt < 4; nt++)
                    MMAFP8(acc[mt][nt], A[ks][mt], b[nt]);
        }

        // epilogue: per-q max over this warp's 32 v
        const float NEG = __int_as_float(0xff800000);
        #pragma unroll
        for (int mt = 0; mt < 4; mt++) {
            float m0 = NEG, m1 = NEG;
            #pragma unroll
            for (int nt = 0; nt < 4; nt++) {
                m0 = fmaxf(m0, fmaxf(acc[mt][nt][0], acc[mt][nt][1]));
                m1 = fmaxf(m1, fmaxf(acc[mt][nt][2], acc[mt][nt][3]));
            }
            m0 = fmaxf(m0, __shfl_xor_sync(0xffffffffu, m0, 1));
            m0 = fmaxf(m0, __shfl_xor_sync(0xffffffffu, m0, 2));
            m1 = fmaxf(m1, __shfl_xor_sync(0xffffffffu, m1, 1));
            m1 = fmaxf(m1, __shfl_xor_sync(0xffffffffu, m1, 2));
            if (tg == 0) {
                int qb = wm * 64 + mt * 16 + g;
                atomicMax(&red[qb], okey(m0));
                atomicMax(&red[qb + 8], okey(m1));
            }
        }
        __syncthreads();
        if (tid < 128) {
            rowreg[ri & 7] = unokey(red[tid]);
            red[tid] = 0;
            if ((ri & 7) == 7) {
                float* dst = g_rowmax + (size_t)(qt * 128 + tid) * NR
                           + rg * 32 + (ri & ~7);
                ((float4*)dst)[0] = make_float4(rowreg[0], rowreg[1], rowreg[2], rowreg[3]);
                ((float4*)dst)[1] = make_float4(rowreg[4], rowreg[5], rowreg[6], rowreg[7]);
            }
        }
    }
}

// ============================================================================
// Phase B: per-query candidate selection (approx rank-40 threshold, cap 96).
// ============================================================================
__global__ void select_kernel() {
    __shared__ u32 hist[256];
    __shared__ u32 s_b1, s_need, s_thr, s_cnt;
    const int tid = threadIdx.x;
    const int q = blockIdx.x;
    const float* sc = g_rowmax + (size_t)q * NR;

    hist[tid] = 0;
    __syncthreads();
    for (int j = tid; j < NR; j += 256) atomicAdd(&hist[okey(sc[j]) >> 24], 1u);
    __syncthreads();
    if (tid == 0) {
        u32 cum = 0;
        for (int b = 255; b >= 0; b--) {
            if (cum + hist[b] >= 40u) { s_b1 = (u32)b; s_need = 40u - cum; break; }
            cum += hist[b];
        }
    }
    __syncthreads();
    u32 b1 = s_b1, need = s_need;
    hist[tid] = 0;
    __syncthreads();
    for (int j = tid; j < NR; j += 256) {
        u32 u = okey(sc[j]);
        if ((u >> 24) == b1) atomicAdd(&hist[(u >> 16) & 255u], 1u);
    }
    __syncthreads();
    if (tid == 0) {
        u32 cum = 0; u32 b2 = 0;
        for (int b = 255; b >= 0; b--) { cum += hist[b]; if (cum >= need) { b2 = (u32)b; break; } }
        s_thr = (b1 << 8) | b2;
        s_cnt = 0;
    }
    __syncthreads();
    u32 thr = s_thr;
    for (int j = tid; j < NR; j += 256) {
        u32 u = okey(sc[j]);
        if ((u >> 16) >= thr) {
            u32 pos = atomicAdd(&s_cnt, 1u);
            if (pos < CAND) {
                g_cand_row[(size_t)q * CAND + pos] = j;
                int p2 = atomicAdd(&g_rowcnt[j], 1);
                if (p2 < RCAP) g_rowlist[(size_t)j * RCAP + p2] = ((u32)q << 7) | pos;
            }
        }
    }
    __syncthreads();
    if (tid == 0) g_cand_cnt[q] = (int)(s_cnt < CAND ? s_cnt : CAND);
}

// ============================================================================
// Phase C: exact recompute, bitwise-matching reference (in-order fp32 FMA
// chain over k=0..127, single accumulator). CTA per row, 256 thr =
// 4 query-slots x 64 vectors; argmax via u64 keys (ties -> lowest v).
// ============================================================================
__global__ void __launch_bounds__(256)
exact_kernel(const float* __restrict__ Q, const float* __restrict__ T) {
    __shared__ __align__(16) float Ts[64 * 132];
    __shared__ __align__(16) float Qs[CQ * 128];
    __shared__ u64 sres[CQ];
    __shared__ u32 sent[CQ];

    const int tid = threadIdx.x;
    const int r = blockIdx.x;
    int nq = g_rowcnt[r];
    if (nq > RCAP) nq = RCAP;
    if (nq == 0) return;
    const int g = tid >> 6;
    const int v = tid & 63;

    #pragma unroll 1
    for (int h = 0; h < 2; h++) {
        __syncthreads();
        {
            const float4* src = (const float4*)(T + (size_t)r * NV * ND
                                                + (size_t)h * 64 * ND);
            #pragma unroll
            for (int i = 0; i < 8; i++) {
                int e = i * 256 + tid;
                int vv = e >> 5, k4 = e & 31;
                *(float4*)(Ts + vv * 132 + k4 * 4) = src[e];
            }
        }
        #pragma unroll 1
        for (int s = 0; s < nq; s += CQ) {
            int cnt = nq - s; if (cnt > CQ) cnt = CQ;
            __syncthreads();
            if (tid < CQ) {
                sres[tid] = 0ull;
                sent[tid] = (tid < cnt) ? g_rowlist[(size_t)r * RCAP + s + tid] : 0u;
            }
            __syncthreads();
            #pragma unroll
            for (int i = 0; i < 2; i++) {
                int e = i * 256 + tid;
                int qq = e >> 5, k4 = e & 31;
                if (qq < cnt) {
                    int qidx = (int)(sent[qq] >> 7);
                    *(float4*)(Qs + qq * 128 + k4 * 4) =
                        ((const float4*)(Q + (size_t)qidx * ND))[k4];
                }
            }
            __syncthreads();

            float a0 = 0.f, a1 = 0.f, a2 = 0.f, a3 = 0.f;
            const float* tv = Ts + v * 132;
            const float* q0 = Qs + (g * 4 + 0) * 128;
            const float* q1 = Qs + (g * 4 + 1) * 128;
            const float* q2 = Qs + (g * 4 + 2) * 128;
            const float* q3 = Qs + (g * 4 + 3) * 128;
            #pragma unroll 8
            for (int k = 0; k < 128; k += 4) {
                float4 t4 = *(const float4*)(tv + k);
                float4 x0 = *(const float4*)(q0 + k);
                float4 x1 = *(const float4*)(q1 + k);
                float4 x2 = *(const float4*)(q2 + k);
                float4 x3 = *(const float4*)(q3 + k);
                a0 = fmas(x0.x, t4.x, a0); a0 = fmas(x0.y, t4.y, a0);
                a0 = fmas(x0.z, t4.z, a0); a0 = fmas(x0.w, t4.w, a0);
                a1 = fmas(x1.x, t4.x, a1); a1 = fmas(x1.y, t4.y, a1);
                a1 = fmas(x1.z, t4.z, a1); a1 = fmas(x1.w, t4.w, a1);
                a2 = fmas(x2.x, t4.x, a2); a2 = fmas(x2.y, t4.y, a2);
                a2 = fmas(x2.z, t4.z, a2); a2 = fmas(x2.w, t4.w, a2);
                a3 = fmas(x3.x, t4.x, a3); a3 = fmas(x3.y, t4.y, a3);
                a3 = fmas(x3.z, t4.z, a3); a3 = fmas(x3.w, t4.w, a3);
            }
            u64 vb = (u64)(u32)(127 - (h * 64 + v));
            atomicMax(&sres[g * 4 + 0], ((u64)okey(a0) << 32) | vb);
            atomicMax(&sres[g * 4 + 1], ((u64)okey(a1) << 32) | vb);
            atomicMax(&sres[g * 4 + 2], ((u64)okey(a2) << 32) | vb);
            atomicMax(&sres[g * 4 + 3], ((u64)okey(a3) << 32) | vb);
            __syncthreads();
            if (tid < cnt) {
                u32 ent = sent[tid];
                int q = (int)(ent >> 7), slot = (int)(ent & 127u);
                atomicMax(&g_cand_key[(size_t)q * CAND + slot], sres[tid]);
            }
        }
    }
}

// ============================================================================
// Phase D: exact top-16 among <=96 candidates + gather (score desc, row desc).
// Output: [values 4096*16*128 | scores 4096*16 | ids 4096*16] (f32).
// ============================================================================
__global__ void final_kernel(const float* __restrict__ T, float* __restrict__ out) {
    int gw = (blockIdx.x * blockDim.x + threadIdx.x) >> 5;
    int lane = threadIdx.x & 31;
    if (gw >= NQ) return;
    const int q = gw;
    int cnt = g_cand_cnt[q];

    u64 key[3]; int argv[3];
    #pragma unroll
    for (int s = 0; s < 3; s++) {
        int idx = lane + 32 * s;
        key[s] = 0; argv[s] = 0;
        if (idx < cnt) {
            u64 ck = g_cand_key[(size_t)q * CAND + idx];
            int rw = g_cand_row[(size_t)q * CAND + idx];
            argv[s] = 127 - (int)(ck & 127u);
            key[s] = (ck & 0xffffffff00000000ull) | (u32)rw;
        }
    }

    for (int i = 0; i < KTOP; i++) {
        u64 m = 0;
        #pragma unroll
        for (int s = 0; s < 3; s++) m = key[s] > m ? key[s] : m;
        #pragma unroll
        for (int off = 16; off; off >>= 1) {
            u64 o = __shfl_xor_sync(0xffffffffu, m, off);
            if (o > m) m = o;
        }
        int have = 0;
        #pragma unroll
        for (int s = 2; s >= 0; s--) if (m && key[s] == m) have = s + 1;
        int myarg = have ? argv[have - 1] : 0;
        unsigned bal = __ballot_sync(0xffffffffu, have != 0);
        int srcl = __ffs(bal) - 1;
        int av = __shfl_sync(0xffffffffu, myarg, srcl);
        int hs = __shfl_sync(0xffffffffu, have, srcl);
        if (lane == srcl) key[hs - 1] = 0;
        int row = (int)(m & 0xffffffffull);
        float score = unokey((u32)(m >> 32));

        const float4* src = (const float4*)(T + ((size_t)row * NV + av) * ND);
        float4* dst = (float4*)(out + ((size_t)q * KTOP + i) * ND);
        dst[lane] = src[lane];
        if (lane == 0) {
            out[(size_t)NQ * KTOP * ND + (size_t)q * KTOP + i] = score;
            out[(size_t)NQ * KTOP * ND + (size_t)NQ * KTOP + (size_t)q * KTOP + i] =
                (float)(row * NV + av);
        }
    }
}

// ============================================================================
extern "C" void kernel_launch(void* const* d_in, const int* in_sizes, int n_in,
                              void* d_out, int out_size) {
    const float* Q = (const float*)d_in[0];
    const float* T = (const float*)d_in[1];
    if (n_in >= 2 && in_sizes[0] > in_sizes[1]) { const float* t = Q; Q = T; T = t; }

    init_kernel<<<(NQ * CAND + 255) / 256, 256>>>();
    conv_T_kernel<<<32768, 256>>>(T);    // 67.1M floats / 8 per thread
    conv_Q_kernel<<<256, 256>>>(Q);      // 524288 floats / 8 per thread

    score_mma_kernel<<<dim3(32, 128), 256>>>();
    select_kernel<<<NQ, 256>>>();
    exact_kernel<<<NR, 256>>>(Q, T);
    final_kernel<<<(NQ * 32 + 255) / 256, 256>>>(T, (float*)d_out);
}

// round 7
// speedup vs baseline: 6.0935x; 1.0445x over previous
#include <cuda_runtime.h>
#include <cstdint>

typedef unsigned int u32;
typedef unsigned long long u64;

#define NQ   4096
#define NR   4096
#define NV   128
#define ND   128
#define KTOP 16
#define CAND 96
#define RCAP 768
#define CQ   16
#define TSTR 36            // smem line stride (u32) for 32-u32 k-lines

// ---------------- device globals ----------------
__device__ u32 g_Tfp8[(size_t)NR * NV * ND / 4];   // 64 MB e4m3, fragment order
__device__ u32 g_Qfp8[(size_t)NQ * ND / 4];        // 512 KB, fragment order
__device__ u32 g_rowmax[(size_t)NQ * NR];          // 64 MB okey(u32) approx scores
__device__ int g_rowcnt[NR];
__device__ u32 g_rowlist[(size_t)NR * RCAP];       // (q<<7)|slot
__device__ int g_cand_row[(size_t)NQ * CAND];
__device__ u64 g_cand_key[(size_t)NQ * CAND];      // (okey(score)<<32)|(127-v)
__device__ int g_cand_cnt[NQ];

// ---------------- helpers ----------------
__device__ __forceinline__ u32 okey(float f) {
    u32 b = __float_as_uint(f);
    return (b & 0x80000000u) ? ~b : (b | 0x80000000u);
}
__device__ __forceinline__ float unokey(u32 u) {
    u32 b = (u & 0x80000000u) ? (u & 0x7fffffffu) : ~u;
    return __uint_as_float(b);
}
__device__ __forceinline__ float fmas(float a, float b, float c) {
    float d; asm("fma.rn.f32 %0, %1, %2, %3;" : "=f"(d) : "f"(a), "f"(b), "f"(c));
    return d;
}
__device__ __forceinline__ u32 pack_e4m3x4(float4 a) {
    unsigned short h0, h1; u32 r;
    asm("cvt.rn.satfinite.e4m3x2.f32 %0, %1, %2;" : "=h"(h0) : "f"(a.y), "f"(a.x));
    asm("cvt.rn.satfinite.e4m3x2.f32 %0, %1, %2;" : "=h"(h1) : "f"(a.w), "f"(a.z));
    asm("mov.b32 %0, {%1, %2};" : "=r"(r) : "h"(h0), "h"(h1));
    return r;
}

#define MMAFP8(c, A, B0, B1) \
    asm volatile("mma.sync.aligned.m16n8k32.row.col.f32.e4m3.e4m3.f32 " \
        "{%0,%1,%2,%3}, {%4,%5,%6,%7}, {%8,%9}, {%0,%1,%2,%3};" \
        : "+f"((c)[0]), "+f"((c)[1]), "+f"((c)[2]), "+f"((c)[3]) \
        : "r"((A)[0]), "r"((A)[1]), "r"((A)[2]), "r"((A)[3]), "r"(B0), "r"(B1))

#define MMAFP8_INIT(c, A, B0, B1, Z) \
    asm volatile("mma.sync.aligned.m16n8k32.row.col.f32.e4m3.e4m3.f32 " \
        "{%0,%1,%2,%3}, {%4,%5,%6,%7}, {%8,%9}, {%10,%10,%10,%10};" \
        : "=f"((c)[0]), "=f"((c)[1]), "=f"((c)[2]), "=f"((c)[3]) \
        : "r"((A)[0]), "r"((A)[1]), "r"((A)[2]), "r"((A)[3]), "r"(B0), "r"(B1), \
          "f"(Z))

// ---------------- conversion (fragment-order layout) ----------------
// new u32 index within a 32-u32 k-line: n = tg*8 + ks*2 + h
// orig u32 index:                        o = ks*8 + h*4 + tg
__global__ void conv_T_kernel(const float* __restrict__ T) {
    int t = blockIdx.x * 256 + threadIdx.x;      // NR*NV*4 threads
    int tg = t & 3, v = (t >> 2) & 127, r = t >> 9;
    const float* src = T + (size_t)r * 16384 + v * 128;
    u32 out[8];
    #pragma unroll
    for (int ks = 0; ks < 4; ks++)
        #pragma unroll
        for (int h = 0; h < 2; h++) {
            float4 f = *(const float4*)(src + ks * 32 + h * 16 + tg * 4);
            out[ks * 2 + h] = pack_e4m3x4(f);
        }
    uint4* dst = (uint4*)g_Tfp8 + (size_t)r * 1024 + v * 8 + tg * 2;
    dst[0] = make_uint4(out[0], out[1], out[2], out[3]);
    dst[1] = make_uint4(out[4], out[5], out[6], out[7]);
}
__global__ void conv_Q_kernel(const float* __restrict__ Q) {
    int t = blockIdx.x * 256 + threadIdx.x;      // NQ*4 threads
    int tg = t & 3, q = t >> 2;
    const float* src = Q + (size_t)q * 128;
    u32 out[8];
    #pragma unroll
    for (int ks = 0; ks < 4; ks++)
        #pragma unroll
        for (int h = 0; h < 2; h++) {
            float4 f = *(const float4*)(src + ks * 32 + h * 16 + tg * 4);
            out[ks * 2 + h] = pack_e4m3x4(f);
        }
    uint4* dst = (uint4*)g_Qfp8 + (size_t)q * 8 + tg * 2;
    dst[0] = make_uint4(out[0], out[1], out[2], out[3]);
    dst[1] = make_uint4(out[4], out[5], out[6], out[7]);
}
__global__ void init_kernel() {
    int i = blockIdx.x * 256 + threadIdx.x;
    if (i < NR) g_rowcnt[i] = 0;
    if (i < NQ * CAND) g_cand_key[i] = 0ull;
}

// ============================================================================
// Phase A: fp8 mma.sync scoring. CTA = (qtile 128q, 32 rows), 256 thr,
// 8 warps (2m x 4n), warp = 64q x 32v. A fragments hoisted to registers.
// Double-buffered T tile, one __syncthreads per row, STS-based epilogue
// (okey partial maxes, consumed one row late), g_rowmax holds okey u32.
// ============================================================================
__global__ void __launch_bounds__(256, 1)
score_mma_kernel() {
    // pool: Ts0 | Ts1(=Qs in prologue) | red0 | red1 | rowbuf
    __shared__ __align__(16) u32 pool[2 * 128 * TSTR + 2 * 512 + 128 * 12];
    u32* Ts0 = pool;
    u32* Ts1 = pool + 128 * TSTR;
    u32* red0 = pool + 2 * 128 * TSTR;
    u32* red1 = red0 + 512;
    u32* rowbuf = red1 + 512;           // 128 threads x 12 (8 used)

    const int tid  = threadIdx.x;
    const int lane = tid & 31;
    const int wid  = tid >> 5;
    const int wm   = wid >> 2;
    const int wn   = wid & 3;
    const int g    = lane >> 2;
    const int tg   = lane & 3;
    const int qt   = blockIdx.x;        // 0..31 (fast -> L2 row sharing)
    const int rg   = blockIdx.y;        // 0..127

    // ---- prologue: stage Q tile (into Ts1 region), prefetch row 0 ----
    {
        const uint4* qsrc = (const uint4*)g_Qfp8 + (size_t)(qt * 128) * 8;
        #pragma unroll
        for (int i = 0; i < 4; i++) {
            int e = i * 256 + tid;           // uint4 idx: q = e>>3, p = e&7
            int q = e >> 3, p = e & 7;
            *(uint4*)(Ts1 + q * TSTR + p * 4) = qsrc[e];
        }
    }
    const uint4* tbase = (const uint4*)g_Tfp8 + (size_t)(rg * 32) * 1024;
    uint4 pf[4];
    #pragma unroll
    for (int i = 0; i < 4; i++) pf[i] = __ldg(tbase + i * 256 + tid);
    __syncthreads();

    // ---- hoist A fragments (full K) from Ts1/Qs ----
    u32 A[4][4][4];
    #pragma unroll
    for (int ks = 0; ks < 4; ks++)
        #pragma unroll
        for (int mt = 0; mt < 4; mt++) {
            int qlo = wm * 64 + mt * 16 + g;
            const u32* p0 = Ts1 + qlo * TSTR + tg * 8 + ks * 2;
            uint2 a02 = *(const uint2*)p0;
            uint2 a13 = *(const uint2*)(p0 + 8 * TSTR);
            A[ks][mt][0] = a02.x; A[ks][mt][2] = a02.y;
            A[ks][mt][1] = a13.x; A[ks][mt][3] = a13.y;
        }
    // stage row 0 into Ts0; prefetch row 1
    #pragma unroll
    for (int i = 0; i < 4; i++) {
        int e = i * 256 + tid;
        int v = e >> 3, p = e & 7;
        *(uint4*)(Ts0 + v * TSTR + p * 4) = pf[i];
    }
    #pragma unroll
    for (int i = 0; i < 4; i++) pf[i] = __ldg(tbase + 1024 + i * 256 + tid);
    __syncthreads();

    const float ZF = 0.0f;

    #pragma unroll 1
    for (int ri = 0; ri < 32; ri++) {
        u32* cur = (ri & 1) ? Ts1 : Ts0;
        u32* nxt = (ri & 1) ? Ts0 : Ts1;
        u32* redw = (ri & 1) ? red1 : red0;
        u32* redr = (ri & 1) ? red0 : red1;

        // stage next row from pf; prefetch row ri+2
        if (ri + 1 < 32) {
            #pragma unroll
            for (int i = 0; i < 4; i++) {
                int e = i * 256 + tid;
                int v = e >> 3, p = e & 7;
                *(uint4*)(nxt + v * TSTR + p * 4) = pf[i];
            }
            if (ri + 2 < 32) {
                #pragma unroll
                for (int i = 0; i < 4; i++)
                    pf[i] = __ldg(tbase + (size_t)(ri + 2) * 1024 + i * 256 + tid);
            }
        }

        // ---- MMAs on cur ----
        float acc[4][4][4];
        #pragma unroll
        for (int nt = 0; nt < 4; nt++) {
            const u32* tr = cur + (wn * 32 + nt * 8 + g) * TSTR + tg * 8;
            uint4 b0 = *(const uint4*)tr;
            uint4 b1 = *(const uint4*)(tr + 4);
            u32 B8[8] = {b0.x, b0.y, b0.z, b0.w, b1.x, b1.y, b1.z, b1.w};
            #pragma unroll
            for (int mt = 0; mt < 4; mt++)
                MMAFP8_INIT(acc[mt][nt], A[0][mt], B8[0], B8[1], ZF);
            #pragma unroll
            for (int ks = 1; ks < 4; ks++)
                #pragma unroll
                for (int mt = 0; mt < 4; mt++)
                    MMAFP8(acc[mt][nt], A[ks][mt], B8[ks * 2], B8[ks * 2 + 1]);
        }

        // ---- epilogue: per-q max over this warp's 32 v -> red STS ----
        #pragma unroll
        for (int mt = 0; mt < 4; mt++) {
            float m0 = fmaxf(fmaxf(acc[mt][0][0], acc[mt][0][1]),
                             fmaxf(acc[mt][1][0], acc[mt][1][1]));
            m0 = fmaxf(m0, fmaxf(fmaxf(acc[mt][2][0], acc[mt][2][1]),
                                 fmaxf(acc[mt][3][0], acc[mt][3][1])));
            float m1 = fmaxf(fmaxf(acc[mt][0][2], acc[mt][0][3]),
                             fmaxf(acc[mt][1][2], acc[mt][1][3]));
            m1 = fmaxf(m1, fmaxf(fmaxf(acc[mt][2][2], acc[mt][2][3]),
                                 fmaxf(acc[mt][3][2], acc[mt][3][3])));
            m0 = fmaxf(m0, __shfl_xor_sync(0xffffffffu, m0, 1));
            m0 = fmaxf(m0, __shfl_xor_sync(0xffffffffu, m0, 2));
            m1 = fmaxf(m1, __shfl_xor_sync(0xffffffffu, m1, 1));
            m1 = fmaxf(m1, __shfl_xor_sync(0xffffffffu, m1, 2));
            if (tg == 0) {
                int q0 = wm * 64 + mt * 16 + g;
                redw[q0 * 4 + wn] = okey(m0);
                redw[(q0 + 8) * 4 + wn] = okey(m1);
            }
        }

        // ---- consume previous row's partials (one row late) ----
        if (ri > 0 && tid < 128) {
            int rj = ri - 1;
            uint4 rv = *(const uint4*)(redr + tid * 4);
            u32 m = rv.x > rv.y ? rv.x : rv.y;
            u32 n2 = rv.z > rv.w ? rv.z : rv.w;
            m = m > n2 ? m : n2;
            rowbuf[tid * 12 + (rj & 7)] = m;
            if ((rj & 7) == 7) {
                uint4 x0 = *(const uint4*)(rowbuf + tid * 12);
                uint4 x1 = *(const uint4*)(rowbuf + tid * 12 + 4);
                u32* dst = g_rowmax + (size_t)(qt * 128 + tid) * NR
                         + rg * 32 + (rj & ~7);
                ((uint4*)dst)[0] = x0;
                ((uint4*)dst)[1] = x1;
            }
        }
        __syncthreads();
    }
    // drain rj = 31
    if (tid < 128) {
        uint4 rv = *(const uint4*)(red1 + tid * 4);   // row 31 wrote red1
        u32 m = rv.x > rv.y ? rv.x : rv.y;
        u32 n2 = rv.z > rv.w ? rv.z : rv.w;
        m = m > n2 ? m : n2;
        rowbuf[tid * 12 + 7] = m;
        uint4 x0 = *(const uint4*)(rowbuf + tid * 12);
        uint4 x1 = *(const uint4*)(rowbuf + tid * 12 + 4);
        u32* dst = g_rowmax + (size_t)(qt * 128 + tid) * NR + rg * 32 + 24;
        ((uint4*)dst)[0] = x0;
        ((uint4*)dst)[1] = x1;
    }
}

// ============================================================================
// Phase B: per-query candidate selection (rank-40 threshold, cap 96).
// g_rowmax already holds okey u32.
// ============================================================================
__global__ void select_kernel() {
    __shared__ u32 hist[256];
    __shared__ u32 s_b1, s_need, s_thr, s_cnt;
    const int tid = threadIdx.x;
    const int q = blockIdx.x;
    const u32* sc = g_rowmax + (size_t)q * NR;

    hist[tid] = 0;
    __syncthreads();
    for (int j = tid; j < NR; j += 256) atomicAdd(&hist[sc[j] >> 24], 1u);
    __syncthreads();
    if (tid == 0) {
        u32 cum = 0;
        for (int b = 255; b >= 0; b--) {
            if (cum + hist[b] >= 40u) { s_b1 = (u32)b; s_need = 40u - cum; break; }
            cum += hist[b];
        }
    }
    __syncthreads();
    u32 b1 = s_b1, need = s_need;
    hist[tid] = 0;
    __syncthreads();
    for (int j = tid; j < NR; j += 256) {
        u32 u = sc[j];
        if ((u >> 24) == b1) atomicAdd(&hist[(u >> 16) & 255u], 1u);
    }
    __syncthreads();
    if (tid == 0) {
        u32 cum = 0; u32 b2 = 0;
        for (int b = 255; b >= 0; b--) { cum += hist[b]; if (cum >= need) { b2 = (u32)b; break; } }
        s_thr = (b1 << 8) | b2;
        s_cnt = 0;
    }
    __syncthreads();
    u32 thr = s_thr;
    for (int j = tid; j < NR; j += 256) {
        if ((sc[j] >> 16) >= thr) {
            u32 pos = atomicAdd(&s_cnt, 1u);
            if (pos < CAND) {
                g_cand_row[(size_t)q * CAND + pos] = j;
                int p2 = atomicAdd(&g_rowcnt[j], 1);
                if (p2 < RCAP) g_rowlist[(size_t)j * RCAP + p2] = ((u32)q << 7) | pos;
            }
        }
    }
    __syncthreads();
    if (tid == 0) g_cand_cnt[q] = (int)(s_cnt < CAND ? s_cnt : CAND);
}

// ============================================================================
// Phase C: exact recompute, bitwise-matching reference (in-order fp32 FMA
// chain over k=0..127, single accumulator). CTA per row.
// ============================================================================
__global__ void __launch_bounds__(256)
exact_kernel(const float* __restrict__ Q, const float* __restrict__ T) {
    __shared__ __align__(16) float Ts[64 * 132];
    __shared__ __align__(16) float Qs[CQ * 128];
    __shared__ u64 sres[CQ];
    __shared__ u32 sent[CQ];

    const int tid = threadIdx.x;
    const int r = blockIdx.x;
    int nq = g_rowcnt[r];
    if (nq > RCAP) nq = RCAP;
    if (nq == 0) return;
    const int g = tid >> 6;
    const int v = tid & 63;

    #pragma unroll 1
    for (int h = 0; h < 2; h++) {
        __syncthreads();
        {
            const float4* src = (const float4*)(T + (size_t)r * NV * ND
                                                + (size_t)h * 64 * ND);
            #pragma unroll
            for (int i = 0; i < 8; i++) {
                int e = i * 256 + tid;
                int vv = e >> 5, k4 = e & 31;
                *(float4*)(Ts + vv * 132 + k4 * 4) = src[e];
            }
        }
        #pragma unroll 1
        for (int s = 0; s < nq; s += CQ) {
            int cnt = nq - s; if (cnt > CQ) cnt = CQ;
            __syncthreads();
            if (tid < CQ) {
                sres[tid] = 0ull;
                sent[tid] = (tid < cnt) ? g_rowlist[(size_t)r * RCAP + s + tid] : 0u;
            }
            __syncthreads();
            #pragma unroll
            for (int i = 0; i < 2; i++) {
                int e = i * 256 + tid;
                int qq = e >> 5, k4 = e & 31;
                if (qq < cnt) {
                    int qidx = (int)(sent[qq] >> 7);
                    *(float4*)(Qs + qq * 128 + k4 * 4) =
                        ((const float4*)(Q + (size_t)qidx * ND))[k4];
                }
            }
            __syncthreads();

            float a0 = 0.f, a1 = 0.f, a2 = 0.f, a3 = 0.f;
            const float* tv = Ts + v * 132;
            const float* q0 = Qs + (g * 4 + 0) * 128;
            const float* q1 = Qs + (g * 4 + 1) * 128;
            const float* q2 = Qs + (g * 4 + 2) * 128;
            const float* q3 = Qs + (g * 4 + 3) * 128;
            #pragma unroll 8
            for (int k = 0; k < 128; k += 4) {
                float4 t4 = *(const float4*)(tv + k);
                float4 x0 = *(const float4*)(q0 + k);
                float4 x1 = *(const float4*)(q1 + k);
                float4 x2 = *(const float4*)(q2 + k);
                float4 x3 = *(const float4*)(q3 + k);
                a0 = fmas(x0.x, t4.x, a0); a0 = fmas(x0.y, t4.y, a0);
                a0 = fmas(x0.z, t4.z, a0); a0 = fmas(x0.w, t4.w, a0);
                a1 = fmas(x1.x, t4.x, a1); a1 = fmas(x1.y, t4.y, a1);
                a1 = fmas(x1.z, t4.z, a1); a1 = fmas(x1.w, t4.w, a1);
                a2 = fmas(x2.x, t4.x, a2); a2 = fmas(x2.y, t4.y, a2);
                a2 = fmas(x2.z, t4.z, a2); a2 = fmas(x2.w, t4.w, a2);
                a3 = fmas(x3.x, t4.x, a3); a3 = fmas(x3.y, t4.y, a3);
                a3 = fmas(x3.z, t4.z, a3); a3 = fmas(x3.w, t4.w, a3);
            }
            u64 vb = (u64)(u32)(127 - (h * 64 + v));
            atomicMax(&sres[g * 4 + 0], ((u64)okey(a0) << 32) | vb);
            atomicMax(&sres[g * 4 + 1], ((u64)okey(a1) << 32) | vb);
            atomicMax(&sres[g * 4 + 2], ((u64)okey(a2) << 32) | vb);
            atomicMax(&sres[g * 4 + 3], ((u64)okey(a3) << 32) | vb);
            __syncthreads();
            if (tid < cnt) {
                u32 ent = sent[tid];
                int q = (int)(ent >> 7), slot = (int)(ent & 127u);
                atomicMax(&g_cand_key[(size_t)q * CAND + slot], sres[tid]);
            }
        }
    }
}

// ============================================================================
// Phase D: exact top-16 among <=96 candidates + gather (score desc, row desc).
// Output: [values 4096*16*128 | scores 4096*16 | ids 4096*16] (f32).
// ============================================================================
__global__ void final_kernel(const float* __restrict__ T, float* __restrict__ out) {
    int gw = (blockIdx.x * blockDim.x + threadIdx.x) >> 5;
    int lane = threadIdx.x & 31;
    if (gw >= NQ) return;
    const int q = gw;
    int cnt = g_cand_cnt[q];

    u64 key[3]; int argv[3];
    #pragma unroll
    for (int s = 0; s < 3; s++) {
        int idx = lane + 32 * s;
        key[s] = 0; argv[s] = 0;
        if (idx < cnt) {
            u64 ck = g_cand_key[(size_t)q * CAND + idx];
            int rw = g_cand_row[(size_t)q * CAND + idx];
            argv[s] = 127 - (int)(ck & 127u);
            key[s] = (ck & 0xffffffff00000000ull) | (u32)rw;
        }
    }

    for (int i = 0; i < KTOP; i++) {
        u64 m = 0;
        #pragma unroll
        for (int s = 0; s < 3; s++) m = key[s] > m ? key[s] : m;
        #pragma unroll
        for (int off = 16; off; off >>= 1) {
            u64 o = __shfl_xor_sync(0xffffffffu, m, off);
            if (o > m) m = o;
        }
        int have = 0;
        #pragma unroll
        for (int s = 2; s >= 0; s--) if (m && key[s] == m) have = s + 1;
        int myarg = have ? argv[have - 1] : 0;
        unsigned bal = __ballot_sync(0xffffffffu, have != 0);
        int srcl = __ffs(bal) - 1;
        int av = __shfl_sync(0xffffffffu, myarg, srcl);
        int hs = __shfl_sync(0xffffffffu, have, srcl);
        if (lane == srcl) key[hs - 1] = 0;
        int row = (int)(m & 0xffffffffull);
        float score = unokey((u32)(m >> 32));

        const float4* src = (const float4*)(T + ((size_t)row * NV + av) * ND);
        float4* dst = (float4*)(out + ((size_t)q * KTOP + i) * ND);
        dst[lane] = src[lane];
        if (lane == 0) {
            out[(size_t)NQ * KTOP * ND + (size_t)q * KTOP + i] = score;
            out[(size_t)NQ * KTOP * ND + (size_t)NQ * KTOP + (size_t)q * KTOP + i] =
                (float)(row * NV + av);
        }
    }
}

// ============================================================================
extern "C" void kernel_launch(void* const* d_in, const int* in_sizes, int n_in,
                              void* d_out, int out_size) {
    const float* Q = (const float*)d_in[0];
    const float* T = (const float*)d_in[1];
    if (n_in >= 2 && in_sizes[0] > in_sizes[1]) { const float* t = Q; Q = T; T = t; }

    init_kernel<<<(NQ * CAND + 255) / 256, 256>>>();
    conv_T_kernel<<<(NR * NV * 4) / 256, 256>>>(T);
    conv_Q_kernel<<<(NQ * 4) / 256, 256>>>(Q);

    score_mma_kernel<<<dim3(32, 128), 256>>>();
    select_kernel<<<NQ, 256>>>();
    exact_kernel<<<NR, 256>>>(Q, T);
    final_kernel<<<(NQ * 32 + 255) / 256, 256>>>(T, (float*)d_out);
}